// round 3
// baseline (speedup 1.0000x reference)
#include <cuda_runtime.h>

#define BB 64
#define CC 256
#define HH 56
#define WW 56
#define SH 52
#define SW 52
#define NPLANES (BB*CC)                 // 16384
#define SEEDS_PER_PLANE (SH*SW)         // 2704
#define OUT_PER_PLANE (HH*WW)           // 3136
#define COUNT_M 51380224                // NPLANES * OUT_PER_PLANE
#define TOTAL_F4 (COUNT_M/4)            // 12845056

#define P 4                             // planes per dilate block
#define F4PP (SEEDS_PER_PLANE/4)        // 676 float4 per plane
#define F4PB (P*F4PP)                   // 2704 float4 per block
#define NBLK1 (NPLANES/P)               // 4096 dilate blocks

// Scratch (no allocations allowed).
__device__ unsigned long long g_dmask[NPLANES * HH];   // 56 row bitmasks/plane -> 7.3 MB
__device__ unsigned int       g_pcount[NBLK1];
__device__ float              g_scale;

// ---------------------------------------------------------------------------
// Kernel 1: 256 threads, 4 planes per block. Read u, threshold -> nibbles,
// horizontal dilation via shifts (5-wide OR), vertical dilation via row OR,
// store 56 row-bitmasks per plane + per-block dropped count.
// ---------------------------------------------------------------------------
__global__ void __launch_bounds__(256) dilate_kernel(const float4* __restrict__ u4,
                                                     const float* __restrict__ gammap) {
    __shared__ unsigned char      nib[P][SH][16];   // 13 nibbles/row (padded to 16)
    __shared__ unsigned long long rowd[P][SH];      // horizontally-dilated rows
    __shared__ unsigned int       wsum[8];

    const int tid = threadIdx.x;
    const float gamma = *gammap;
    const float4* up = u4 + (size_t)blockIdx.x * F4PB;

    // Coalesced, fully-unrolled load: 11 predicated float4 loads per thread
    // issued up front (high MLP), then cheap byte stores to shared.
    #pragma unroll
    for (int i = 0; i < 11; i++) {
        int f = tid + 256 * i;
        if (f < F4PB) {
            float4 v = up[f];
            int plane = f / F4PP;
            int rem   = f - plane * F4PP;
            int row   = rem / 13;
            int cg    = rem - row * 13;
            unsigned n = (unsigned)(v.x < gamma)        | ((unsigned)(v.y < gamma) << 1)
                       | ((unsigned)(v.z < gamma) << 2) | ((unsigned)(v.w < gamma) << 3);
            nib[plane][row][cg] = (unsigned char)n;
        }
    }
    __syncthreads();

    // Horizontal dilation: bit j = OR of seed bits [j-4, j] over 56 output bits.
    if (tid < P * SH) {
        int plane = tid / SH, row = tid - plane * SH;
        unsigned long long r = 0;
        #pragma unroll
        for (int c = 0; c < 13; c++)
            r |= ((unsigned long long)nib[plane][row][c]) << (4 * c);
        unsigned long long t = r | (r << 1);
        t |= (t << 2);
        r  = t | (r << 4);
        rowd[plane][row] = r;
    }
    __syncthreads();

    // Vertical dilation: output row i = OR of rows [max(0,i-4), min(51,i)].
    unsigned cnt = 0;
    if (tid < P * HH) {
        int plane = tid / HH, row = tid - plane * HH;
        int lo = row - 4; if (lo < 0) lo = 0;
        int hi = row;     if (hi > SH - 1) hi = SH - 1;
        unsigned long long d = 0;
        for (int p = lo; p <= hi; p++) d |= rowd[plane][p];
        g_dmask[((size_t)blockIdx.x * P + plane) * HH + row] = d;
        cnt = __popcll(d);
    }

    // Deterministic block reduction of dropped count (integer-exact).
    #pragma unroll
    for (int o = 16; o; o >>= 1) cnt += __shfl_down_sync(0xffffffffu, cnt, o);
    if ((tid & 31) == 0) wsum[tid >> 5] = cnt;
    __syncthreads();
    if (tid == 0) {
        unsigned s = 0;
        #pragma unroll
        for (int w = 0; w < 8; w++) s += wsum[w];
        g_pcount[blockIdx.x] = s;
    }
}

// ---------------------------------------------------------------------------
// Kernel 2: reduce 4096 block counts, compute normalization scale once.
// ---------------------------------------------------------------------------
__global__ void __launch_bounds__(256) scale_kernel() {
    __shared__ unsigned int s[256];
    unsigned int tot = 0;
    for (int i = threadIdx.x; i < NBLK1; i += 256) tot += g_pcount[i];
    s[threadIdx.x] = tot;
    __syncthreads();
    for (int o = 128; o; o >>= 1) {
        if (threadIdx.x < o) s[threadIdx.x] += s[threadIdx.x + o];
        __syncthreads();
    }
    if (threadIdx.x == 0) {
        double ones = (double)COUNT_M - (double)s[0];   // kept elements
        g_scale = (float)((double)COUNT_M / (ones + 1e-12));
    }
}

// ---------------------------------------------------------------------------
// Kernel 3: apply. One float4 per thread; 4 mask bits come from the correct
// 32-bit half of the row word (nibbles never straddle the 32-bit boundary:
// 4*cg ∈ {0..52}, cg=8 starts exactly at bit 32).
// ---------------------------------------------------------------------------
__global__ void __launch_bounds__(256) apply_kernel(const float* __restrict__ x,
                                                    float* __restrict__ out) {
    const float s = g_scale;
    unsigned f = blockIdx.x * 256u + threadIdx.x;      // float4 index

    unsigned plane = f / 784u;                         // 784 f4 per plane
    unsigned rem   = f - plane * 784u;
    unsigned row   = rem / 14u;                        // 14 f4 per 56-wide row
    unsigned cg    = rem - row * 14u;

    const unsigned* dm32 = (const unsigned*)g_dmask;
    unsigned word  = dm32[((size_t)plane * HH + row) * 2 + (cg >> 3)];
    unsigned bits  = (word >> ((cg & 7u) * 4u)) & 0xFu;

    float4 v = ((const float4*)x)[f];
    float4 o;
    o.x = (bits & 1u) ? 0.0f : v.x * s;
    o.y = (bits & 2u) ? 0.0f : v.y * s;
    o.z = (bits & 4u) ? 0.0f : v.z * s;
    o.w = (bits & 8u) ? 0.0f : v.w * s;
    ((float4*)out)[f] = o;
}

// ---------------------------------------------------------------------------
extern "C" void kernel_launch(void* const* d_in, const int* in_sizes, int n_in,
                              void* d_out, int out_size) {
    const float* x = nullptr;
    const float* u = nullptr;
    const float* g = nullptr;
    for (int i = 0; i < n_in; i++) {
        if (in_sizes[i] == COUNT_M)                        x = (const float*)d_in[i];
        else if (in_sizes[i] == NPLANES * SEEDS_PER_PLANE) u = (const float*)d_in[i];
        else if (in_sizes[i] == 1)                         g = (const float*)d_in[i];
    }
    float* out = (float*)d_out;

    dilate_kernel<<<NBLK1, 256>>>((const float4*)u, g);
    scale_kernel<<<1, 256>>>();
    apply_kernel<<<TOTAL_F4 / 256, 256>>>(x, out);
}

// round 4
// speedup vs baseline: 1.0790x; 1.0790x over previous
#include <cuda_runtime.h>

#define BB 64
#define CC 256
#define HH 56
#define WW 56
#define SH 52
#define SW 52
#define NPLANES (BB*CC)                 // 16384
#define SEEDS_PER_PLANE (SH*SW)         // 2704
#define OUT_PER_PLANE (HH*WW)           // 3136
#define COUNT_M 51380224                // NPLANES * OUT_PER_PLANE
#define TOTAL_F4 (COUNT_M/4)            // 12845056

#define P 8                             // planes per block = warps per block
#define F4PP (SEEDS_PER_PLANE/4)        // 676 float4 per plane
#define NBLK1 (NPLANES/P)               // 2048 dilate blocks

// Scratch (no allocations allowed).
__device__ unsigned long long g_dmask[NPLANES * HH];   // 56 row bitmasks/plane -> 7.3 MB
__device__ unsigned int       g_pcount[NPLANES];       // per-plane dropped counts
__device__ float              g_scale;

// Pack 4 bytes (each holding a 4-bit value in its low nibble) into 16 bits.
__device__ __forceinline__ unsigned pack16(unsigned w) {
    unsigned t = w | (w >> 4);
    t &= 0x00FF00FFu;
    return (t | (t >> 8)) & 0xFFFFu;
}

// ---------------------------------------------------------------------------
// Kernel 1: fully warp-synchronous. One plane per warp, 8 warps per block,
// zero __syncthreads. Threshold -> nibbles in smem, horizontal dilation via
// bit shifts, vertical via row OR, per-plane count written directly.
// ---------------------------------------------------------------------------
__global__ void __launch_bounds__(256) dilate_kernel(const float4* __restrict__ u4,
                                                     const float* __restrict__ gammap) {
    __shared__ unsigned char      nib[P][SH][16];   // 13 nibbles/row, 16B-aligned rows
    __shared__ unsigned long long rowd[P][SH];      // horizontally-dilated rows

    const int warp = threadIdx.x >> 5;
    const int lane = threadIdx.x & 31;
    const int plane = blockIdx.x * P + warp;
    const float gamma = __ldg(gammap);

    // Coalesced streaming load of this warp's plane: 676 float4s, 22 unrolled
    // predicated iterations -> deep MLP, no cross-warp dependencies.
    const float4* up = u4 + (size_t)plane * F4PP;
    #pragma unroll
    for (int i = 0; i < 22; i++) {
        int f = 32 * i + lane;
        if (f < F4PP) {
            float4 v = __ldcs(&up[f]);
            int row = f / 13;
            int cg  = f - row * 13;
            unsigned n = (unsigned)(v.x < gamma)        | ((unsigned)(v.y < gamma) << 1)
                       | ((unsigned)(v.z < gamma) << 2) | ((unsigned)(v.w < gamma) << 3);
            nib[warp][row][cg] = (unsigned char)n;
        }
    }
    __syncwarp();

    // Horizontal dilation: one LDS.128 per row, nibble-pack to a 52-bit word,
    // then bit j = OR of seed bits [j-4, j]  (r | r<<1 | ... | r<<4).
    for (int r = lane; r < SH; r += 32) {
        uint4 w = *(const uint4*)&nib[warp][r][0];
        unsigned long long rr =
              (unsigned long long)(pack16(w.x) | (pack16(w.y) << 16))
            | ((unsigned long long)(pack16(w.z) | (pack16(w.w) << 16)) << 32);
        rr &= 0x000FFFFFFFFFFFFFull;     // keep the 52 valid seed bits
        unsigned long long t = rr | (rr << 1);
        t |= (t << 2);
        rr = t | (rr << 4);
        rowd[warp][r] = rr;
    }
    __syncwarp();

    // Vertical dilation: output row i = OR of rows [max(0,i-4), min(51,i)].
    unsigned cnt = 0;
    for (int i = lane; i < HH; i += 32) {
        int lo = i - 4; if (lo < 0) lo = 0;
        int hi = i;     if (hi > SH - 1) hi = SH - 1;
        unsigned long long d = 0;
        for (int p = lo; p <= hi; p++) d |= rowd[warp][p];
        g_dmask[(size_t)plane * HH + i] = d;
        cnt += __popcll(d);
    }

    // Warp reduction, per-plane count (deterministic, no atomics).
    #pragma unroll
    for (int o = 16; o; o >>= 1) cnt += __shfl_down_sync(0xffffffffu, cnt, o);
    if (lane == 0) g_pcount[plane] = cnt;
}

// ---------------------------------------------------------------------------
// Kernel 2: reduce 16384 per-plane counts, compute normalization scale once.
// ---------------------------------------------------------------------------
__global__ void __launch_bounds__(256) scale_kernel() {
    __shared__ unsigned int s[256];
    unsigned int tot = 0;
    for (int i = threadIdx.x; i < NPLANES; i += 256) tot += g_pcount[i];
    s[threadIdx.x] = tot;
    __syncthreads();
    for (int o = 128; o; o >>= 1) {
        if (threadIdx.x < o) s[threadIdx.x] += s[threadIdx.x + o];
        __syncthreads();
    }
    if (threadIdx.x == 0) {
        double ones = (double)COUNT_M - (double)s[0];   // kept elements
        g_scale = (float)((double)COUNT_M / (ones + 1e-12));
    }
}

// ---------------------------------------------------------------------------
// Kernel 3: apply, ILP-2. Two float4s per thread; mask bits come from the
// correct 32-bit half of the row word (4*cg never straddles bit 32).
// Streaming hints keep the small mask resident in L2 while x/out stream.
// ---------------------------------------------------------------------------
__device__ __forceinline__ void apply_one(const float* __restrict__ x,
                                          float* __restrict__ out,
                                          unsigned f, float s) {
    unsigned plane = f / 784u;                         // 784 f4 per plane
    unsigned rem   = f - plane * 784u;
    unsigned row   = rem / 14u;                        // 14 f4 per 56-wide row
    unsigned cg    = rem - row * 14u;

    const unsigned* dm32 = (const unsigned*)g_dmask;
    unsigned word  = dm32[((size_t)plane * HH + row) * 2 + (cg >> 3)];
    unsigned bits  = (word >> ((cg & 7u) * 4u)) & 0xFu;

    float4 v = __ldcs((const float4*)x + f);
    float4 o;
    o.x = (bits & 1u) ? 0.0f : v.x * s;
    o.y = (bits & 2u) ? 0.0f : v.y * s;
    o.z = (bits & 4u) ? 0.0f : v.z * s;
    o.w = (bits & 8u) ? 0.0f : v.w * s;
    __stcs((float4*)out + f, o);
}

__global__ void __launch_bounds__(256) apply_kernel(const float* __restrict__ x,
                                                    float* __restrict__ out) {
    const float s = g_scale;
    unsigned base = blockIdx.x * 512u + threadIdx.x;
    apply_one(x, out, base, s);
    apply_one(x, out, base + 256u, s);
}

// ---------------------------------------------------------------------------
extern "C" void kernel_launch(void* const* d_in, const int* in_sizes, int n_in,
                              void* d_out, int out_size) {
    const float* x = nullptr;
    const float* u = nullptr;
    const float* g = nullptr;
    for (int i = 0; i < n_in; i++) {
        if (in_sizes[i] == COUNT_M)                        x = (const float*)d_in[i];
        else if (in_sizes[i] == NPLANES * SEEDS_PER_PLANE) u = (const float*)d_in[i];
        else if (in_sizes[i] == 1)                         g = (const float*)d_in[i];
    }
    float* out = (float*)d_out;

    dilate_kernel<<<NBLK1, 256>>>((const float4*)u, g);
    scale_kernel<<<1, 256>>>();
    apply_kernel<<<TOTAL_F4 / 512, 256>>>(x, out);
}

// round 6
// speedup vs baseline: 1.1196x; 1.0376x over previous
#include <cuda_runtime.h>

#define BB 64
#define CC 256
#define HH 56
#define WW 56
#define SH 52
#define SW 52
#define NPLANES (BB*CC)                 // 16384
#define SEEDS_PER_PLANE (SH*SW)         // 2704
#define OUT_PER_PLANE (HH*WW)           // 3136
#define COUNT_M 51380224                // NPLANES * OUT_PER_PLANE
#define TOTAL_F4 (COUNT_M/4)            // 12845056

#define P 8                             // planes per block = warps per block
#define F4PP (SEEDS_PER_PLANE/4)        // 676 float4 per plane
#define NBLK1 (NPLANES/P)               // 2048 dilate blocks

// Scratch (no allocations allowed).
__device__ unsigned long long g_dmask[NPLANES * HH];   // 56 row bitmasks/plane -> 7.3 MB
__device__ unsigned int       g_total = 0;             // dropped-count accumulator
__device__ float              g_scale;

// Pack 4 bytes (each holding a 4-bit value in its low nibble) into 16 bits.
__device__ __forceinline__ unsigned pack16(unsigned w) {
    unsigned t = w | (w >> 4);
    t &= 0x00FF00FFu;
    return (t | (t >> 8)) & 0xFFFFu;
}

// ---------------------------------------------------------------------------
// Kernel 1: fully warp-synchronous, one plane per warp, zero __syncthreads.
// Loads are explicitly batched (11 float4s issued before any consumption) so
// each warp keeps ~11 LDG.128 in flight; launch bounds raise the reg budget.
// Per-warp dropped count goes to a single global accumulator via integer
// atomicAdd (associative -> deterministic), overlapped with the kernel tail.
// ---------------------------------------------------------------------------
__global__ void __launch_bounds__(256, 3) dilate_kernel(const float4* __restrict__ u4,
                                                        const float* __restrict__ gammap) {
    __shared__ unsigned char      nib[P][SH][16];   // 13 nibbles/row, 16B rows
    __shared__ unsigned long long rowd[P][SH];      // horizontally-dilated rows

    const int warp = threadIdx.x >> 5;
    const int lane = threadIdx.x & 31;
    const int plane = blockIdx.x * P + warp;
    const float gamma = __ldg(gammap);
    const float4* up = u4 + (size_t)plane * F4PP;

    // Two batches of 11 float4s: issue all loads, then threshold + byte-store.
    #pragma unroll
    for (int b = 0; b < 2; b++) {
        float4 v[11];
        #pragma unroll
        for (int j = 0; j < 11; j++) {
            int f = 32 * (11 * b + j) + lane;
            if (f < F4PP) v[j] = __ldcs(&up[f]);
        }
        #pragma unroll
        for (int j = 0; j < 11; j++) {
            int f = 32 * (11 * b + j) + lane;
            if (f < F4PP) {
                unsigned n = (unsigned)(v[j].x < gamma)
                           | ((unsigned)(v[j].y < gamma) << 1)
                           | ((unsigned)(v[j].z < gamma) << 2)
                           | ((unsigned)(v[j].w < gamma) << 3);
                int row = f / 13;
                int cg  = f - row * 13;
                nib[warp][row][cg] = (unsigned char)n;
            }
        }
    }
    __syncwarp();

    // Horizontal dilation: one LDS.128 per row, nibble-pack to 52 bits,
    // then bit j = OR of seed bits [j-4, j].
    for (int r = lane; r < SH; r += 32) {
        uint4 w = *(const uint4*)&nib[warp][r][0];
        unsigned long long rr =
              (unsigned long long)(pack16(w.x) | (pack16(w.y) << 16))
            | ((unsigned long long)(pack16(w.z) | (pack16(w.w) << 16)) << 32);
        rr &= 0x000FFFFFFFFFFFFFull;     // 52 valid seed bits
        unsigned long long t = rr | (rr << 1);
        t |= (t << 2);
        rr = t | (rr << 4);
        rowd[warp][r] = rr;
    }
    __syncwarp();

    // Vertical dilation: output row i = OR of rows [max(0,i-4), min(51,i)].
    unsigned cnt = 0;
    for (int i = lane; i < HH; i += 32) {
        int lo = i - 4; if (lo < 0) lo = 0;
        int hi = i;     if (hi > SH - 1) hi = SH - 1;
        unsigned long long d = 0;
        for (int p = lo; p <= hi; p++) d |= rowd[warp][p];
        g_dmask[(size_t)plane * HH + i] = d;
        cnt += __popcll(d);
    }

    // Warp-reduce then one fire-and-forget atomic per warp.
    #pragma unroll
    for (int o = 16; o; o >>= 1) cnt += __shfl_down_sync(0xffffffffu, cnt, o);
    if (lane == 0) atomicAdd(&g_total, cnt);
}

// ---------------------------------------------------------------------------
// Kernel 2: single thread. Computes the normalization scale in double and
// re-zeros the accumulator, preserving the zero-invariant for graph replays.
// ---------------------------------------------------------------------------
__global__ void scale_kernel() {
    unsigned tot = g_total;
    double ones = (double)COUNT_M - (double)tot;   // kept elements
    g_scale = (float)((double)COUNT_M / (ones + 1e-12));
    g_total = 0;
}

// ---------------------------------------------------------------------------
// Kernel 3: apply, ILP-2. Mask bits come from the correct 32-bit half of the
// row word (4*cg never straddles bit 32). Streaming hints on x/out keep the
// small mask resident in cache.
// ---------------------------------------------------------------------------
__device__ __forceinline__ void apply_one(const float* __restrict__ x,
                                          float* __restrict__ out,
                                          unsigned f, float s) {
    unsigned plane = f / 784u;                         // 784 f4 per plane
    unsigned rem   = f - plane * 784u;
    unsigned row   = rem / 14u;                        // 14 f4 per 56-wide row
    unsigned cg    = rem - row * 14u;

    const unsigned* dm32 = (const unsigned*)g_dmask;
    unsigned word  = dm32[((size_t)plane * HH + row) * 2 + (cg >> 3)];
    unsigned bits  = (word >> ((cg & 7u) * 4u)) & 0xFu;

    float4 v = __ldcs((const float4*)x + f);
    float4 o;
    o.x = (bits & 1u) ? 0.0f : v.x * s;
    o.y = (bits & 2u) ? 0.0f : v.y * s;
    o.z = (bits & 4u) ? 0.0f : v.z * s;
    o.w = (bits & 8u) ? 0.0f : v.w * s;
    __stcs((float4*)out + f, o);
}

__global__ void __launch_bounds__(256) apply_kernel(const float* __restrict__ x,
                                                    float* __restrict__ out) {
    const float s = g_scale;
    unsigned base = blockIdx.x * 512u + threadIdx.x;
    apply_one(x, out, base, s);
    apply_one(x, out, base + 256u, s);
}

// ---------------------------------------------------------------------------
extern "C" void kernel_launch(void* const* d_in, const int* in_sizes, int n_in,
                              void* d_out, int out_size) {
    const float* x = nullptr;
    const float* u = nullptr;
    const float* g = nullptr;
    for (int i = 0; i < n_in; i++) {
        if (in_sizes[i] == COUNT_M)                        x = (const float*)d_in[i];
        else if (in_sizes[i] == NPLANES * SEEDS_PER_PLANE) u = (const float*)d_in[i];
        else if (in_sizes[i] == 1)                         g = (const float*)d_in[i];
    }
    float* out = (float*)d_out;

    dilate_kernel<<<NBLK1, 256>>>((const float4*)u, g);
    scale_kernel<<<1, 1>>>();
    apply_kernel<<<TOTAL_F4 / 512, 256>>>(x, out);
}